// round 4
// baseline (speedup 1.0000x reference)
#include <cuda_runtime.h>
#include <cuda_bf16.h>

#define N_NODES  50000
#define N_EDGESC 1600000
#define ET       1650000            // edges + self loops
#define F        128
#define FE       32
#define NG       512
#define NC       10
#define SLOPE    0.2f

// ---------------- scratch (device globals: allocation-free rule) -------------
__device__ float g_ee[(size_t)ET * F];     // 845 MB, per-edge transformed attrs (sorted order)
__device__ float g_xl[(size_t)N_NODES * F];
__device__ float g_xr[(size_t)N_NODES * F];
__device__ float g_hA[(size_t)N_NODES * F];
__device__ float g_hB[(size_t)N_NODES * F];
__device__ float g_loop[(size_t)N_NODES * FE];   // self-loop attrs (mean of incoming)
__device__ int   g_deg[N_NODES];
__device__ int   g_rowptr[N_NODES + 1];
__device__ int   g_cnt[N_NODES];
__device__ int   g_srcs[ET];
__device__ int   g_eids[ET];
__device__ float g_pool[NG * F];
__device__ int   g_gcnt[NG];
__device__ int   g_is64;                   // 1 if index arrays are int64, 0 if int32

// ---------------- index dtype handling --------------------------------------
// JAX with default config silently downcasts jnp.int64 -> int32, so the index
// arrays may be either width. Probe once, read through a flag-guarded helper.
__global__ void k_probe(const void* __restrict__ ei) {
    // int64 elements < 2^32 have zero high words at odd word positions.
    const unsigned* w = (const unsigned*)ei;
    if (threadIdx.x == 0) {
        int all0 = 1;
        #pragma unroll
        for (int i = 0; i < 64; i++) all0 &= (w[2 * i + 1] == 0u);
        g_is64 = all0;
    }
}

__device__ __forceinline__ int getIdx(const void* __restrict__ p, long long i) {
    if (g_is64) return (int)((const long long*)p)[i];
    return ((const int*)p)[i];
}

// ---------------- utility --------------------------------------------------
__global__ void k_zero() {
    int i = blockIdx.x * blockDim.x + threadIdx.x;   // grid covers 1.6M
    if (i < N_NODES * FE) g_loop[i] = 0.f;
    if (i < N_NODES) { g_deg[i] = 0; g_cnt[i] = 0; }
    if (i < NG * F) g_pool[i] = 0.f;
    if (i < NG) g_gcnt[i] = 0;
}

// deg + segment-sum of edge_attr over dst (one warp per edge, lane = channel)
__global__ void k_degloop(const void* __restrict__ ei, const float* __restrict__ ea) {
    long long t = (long long)blockIdx.x * blockDim.x + threadIdx.x;
    if (t >= (long long)N_EDGESC * FE) return;
    int e = (int)(t >> 5);
    int c = (int)(t & 31);
    int dst = getIdx(ei, (long long)N_EDGESC + e);
    atomicAdd(&g_loop[dst * FE + c], ea[(long long)e * FE + c]);
    if (c == 0) atomicAdd(&g_deg[dst], 1);
}

// exclusive scan of (deg+1) -> rowptr, single 1024-thread block
__global__ void k_scan() {
    __shared__ int s[1024];
    __shared__ int carry_s;
    int tid = threadIdx.x;
    if (tid == 0) carry_s = 0;
    __syncthreads();
    for (int base = 0; base < N_NODES; base += 1024) {
        int idx = base + tid;
        int v = (idx < N_NODES) ? (g_deg[idx] + 1) : 0;
        int c0 = carry_s;
        s[tid] = v;
        __syncthreads();
        for (int off = 1; off < 1024; off <<= 1) {
            int t = (tid >= off) ? s[tid - off] : 0;
            __syncthreads();
            s[tid] += t;
            __syncthreads();
        }
        if (idx < N_NODES) g_rowptr[idx] = c0 + s[tid] - v;
        int tot = s[1023];
        __syncthreads();
        if (tid == 0) carry_s = c0 + tot;
        __syncthreads();
    }
    if (tid == 0) g_rowptr[N_NODES] = carry_s;   // == ET
}

__global__ void k_loopdiv() {
    int i = blockIdx.x * blockDim.x + threadIdx.x;
    if (i >= N_NODES * FE) return;
    float d = (float)g_deg[i >> 5];
    g_loop[i] = g_loop[i] / fmaxf(d, 1.f);
}

// place self-loops first in each CSR row
__global__ void k_self() {
    int v = blockIdx.x * blockDim.x + threadIdx.x;
    if (v >= N_NODES) return;
    int p = g_rowptr[v];
    g_srcs[p] = v;
    g_eids[p] = N_EDGESC + v;
}

// counting-sort scatter of real edges by dst
__global__ void k_scatter(const void* __restrict__ ei) {
    int e = blockIdx.x * blockDim.x + threadIdx.x;
    if (e >= N_EDGESC) return;
    int src = getIdx(ei, e);
    int dst = getIdx(ei, (long long)N_EDGESC + e);
    int p = g_rowptr[dst] + 1 + atomicAdd(&g_cnt[dst], 1);
    g_srcs[p] = src;
    g_eids[p] = e;
}

// ---------------- per-layer GEMMs ------------------------------------------
// xl = h@Wl + bl ; xr = h@Wr + br.  Block: 128 threads (cols) x 32 rows.
__global__ void __launch_bounds__(128) k_xlxr(
    const float* __restrict__ x_ext, int hin_sel,
    const float* __restrict__ Wl, const float* __restrict__ bl,
    const float* __restrict__ Wr, const float* __restrict__ br) {
    const float* h = (hin_sel == 0) ? x_ext : (hin_sel == 1 ? g_hA : g_hB);
    __shared__ float sh[32][F];
    int j = threadIdx.x;
    int r0 = blockIdx.x * 32;
    #pragma unroll
    for (int r = 0; r < 32; r++) {
        int row = r0 + r;
        sh[r][j] = (row < N_NODES) ? h[(long long)row * F + j] : 0.f;
    }
    __syncthreads();
    float aL[32], aR[32];
    float b_l = bl[j], b_r = br[j];
    #pragma unroll
    for (int r = 0; r < 32; r++) { aL[r] = b_l; aR[r] = b_r; }
    #pragma unroll 4
    for (int k = 0; k < F; k++) {
        float wl = Wl[k * F + j];
        float wr = Wr[k * F + j];
        #pragma unroll
        for (int r = 0; r < 32; r++) {
            float hv = sh[r][k];
            aL[r] += hv * wl;
            aR[r] += hv * wr;
        }
    }
    #pragma unroll
    for (int r = 0; r < 32; r++) {
        int row = r0 + r;
        if (row < N_NODES) {
            g_xl[(long long)row * F + j] = aL[r];
            g_xr[(long long)row * F + j] = aR[r];
        }
    }
}

// ee[i] = attr(eid[i]) @ We ; warp per sorted slot, We register-resident per lane
__global__ void __launch_bounds__(256) k_ee(
    const float* __restrict__ ea, const float* __restrict__ We) {
    int lane = threadIdx.x & 31;
    float2 w0[FE], w1[FE];
    #pragma unroll
    for (int k = 0; k < FE; k++) {
        w0[k] = *(const float2*)(We + k * F + 2 * lane);
        w1[k] = *(const float2*)(We + k * F + 64 + 2 * lane);
    }
    int w  = (blockIdx.x * blockDim.x + threadIdx.x) >> 5;
    int nw = (gridDim.x * blockDim.x) >> 5;
    for (int i = w; i < ET; i += nw) {
        int e = g_eids[i];
        const float* ap = (e < N_EDGESC) ? (ea + (long long)e * FE)
                                         : (g_loop + (long long)(e - N_EDGESC) * FE);
        float a = ap[lane];
        float a00 = 0.f, a01 = 0.f, a10 = 0.f, a11 = 0.f;
        #pragma unroll
        for (int k = 0; k < FE; k++) {
            float ak = __shfl_sync(0xffffffffu, a, k);
            a00 += ak * w0[k].x; a01 += ak * w0[k].y;
            a10 += ak * w1[k].x; a11 += ak * w1[k].y;
        }
        float* o = g_ee + (long long)i * F;
        *(float2*)(o + 2 * lane)      = make_float2(a00, a01);
        *(float2*)(o + 64 + 2 * lane) = make_float2(a10, a11);
    }
}

// one warp per dst node: online-softmax attention aggregation (single pass)
__global__ void __launch_bounds__(256) k_agg(
    const float* __restrict__ att, const float* __restrict__ bias, int hout_sel) {
    int wid = (blockIdx.x * blockDim.x + threadIdx.x) >> 5;
    if (wid >= N_NODES) return;
    float* hout = (hout_sel == 1) ? g_hB : g_hA;
    int lane = threadIdx.x & 31;
    int v = wid;
    float4 xr = *(const float4*)(g_xr + (long long)v * F + 4 * lane);
    float4 at = *(const float4*)(att + 4 * lane);
    int beg = g_rowptr[v], end = g_rowptr[v + 1];
    float m = -3.0e38f, denom = 0.f;
    float4 acc = make_float4(0.f, 0.f, 0.f, 0.f);
    for (int i = beg; i < end; i++) {
        int src = g_srcs[i];
        float4 xl = *(const float4*)(g_xl + (long long)src * F + 4 * lane);
        float4 ee = *(const float4*)(g_ee + (long long)i * F + 4 * lane);
        float t0 = xl.x + xr.x + ee.x; t0 = t0 > 0.f ? t0 : SLOPE * t0;
        float t1 = xl.y + xr.y + ee.y; t1 = t1 > 0.f ? t1 : SLOPE * t1;
        float t2 = xl.z + xr.z + ee.z; t2 = t2 > 0.f ? t2 : SLOPE * t2;
        float t3 = xl.w + xr.w + ee.w; t3 = t3 > 0.f ? t3 : SLOPE * t3;
        float p = t0 * at.x + t1 * at.y + t2 * at.z + t3 * at.w;
        #pragma unroll
        for (int off = 16; off; off >>= 1) p += __shfl_xor_sync(0xffffffffu, p, off);
        float mn = fmaxf(m, p);
        float sc = __expf(m - mn);       // underflows to 0 on first edge
        float pe = __expf(p - mn);
        denom = denom * sc + pe;
        acc.x = acc.x * sc + pe * xl.x;
        acc.y = acc.y * sc + pe * xl.y;
        acc.z = acc.z * sc + pe * xl.z;
        acc.w = acc.w * sc + pe * xl.w;
        m = mn;
    }
    float4 bi = *(const float4*)(bias + 4 * lane);
    float inv = 1.f / denom;
    float4 o;
    o.x = fmaxf(acc.x * inv + bi.x, 0.f);
    o.y = fmaxf(acc.y * inv + bi.y, 0.f);
    o.z = fmaxf(acc.z * inv + bi.z, 0.f);
    o.w = fmaxf(acc.w * inv + bi.w, 0.f);
    *(float4*)(hout + (long long)v * F + 4 * lane) = o;
}

// ---------------- pool + classifier ----------------------------------------
__global__ void k_pool(const void* __restrict__ batch) {
    int t = blockIdx.x * blockDim.x + threadIdx.x;   // grid covers N*F exactly
    int v = t >> 7;
    int c = t & 127;
    int g = getIdx(batch, v);
    atomicAdd(&g_pool[g * F + c], g_hA[t]);
    if (c == 0) atomicAdd(&g_gcnt[g], 1);
}

__global__ void k_final(const float* __restrict__ lw, const float* __restrict__ lb,
                        float* __restrict__ out) {
    int t = blockIdx.x * blockDim.x + threadIdx.x;
    if (t >= NG * NC) return;
    int g = t / NC, cls = t % NC;
    float inv = 1.f / fmaxf((float)g_gcnt[g], 1.f);
    float acc = lb[cls];
    #pragma unroll 8
    for (int c = 0; c < F; c++)
        acc += (g_pool[g * F + c] * inv) * lw[c * NC + cls];
    out[t] = acc;
}

// ---------------- host -------------------------------------------------------
extern "C" void kernel_launch(void* const* d_in, const int* in_sizes, int n_in,
                              void* d_out, int out_size) {
    (void)in_sizes; (void)n_in; (void)out_size;
    const float* x     = (const float*)d_in[0];
    const void*  ei    = d_in[1];               // int32 or int64 (probed)
    const void*  batch = d_in[2];               // int32 or int64 (probed)
    // d_in[3] = dropout (identity in eval)
    const float* ea   = (const float*)d_in[4];
    const float* Wl   = (const float*)d_in[5];
    const float* bl   = (const float*)d_in[6];
    const float* Wr   = (const float*)d_in[7];
    const float* br   = (const float*)d_in[8];
    const float* We   = (const float*)d_in[9];
    const float* att  = (const float*)d_in[10];
    const float* bias = (const float*)d_in[11];
    const float* lw   = (const float*)d_in[12];
    const float* lb   = (const float*)d_in[13];
    float* out = (float*)d_out;

    k_probe<<<1, 32>>>(ei);
    k_zero<<<6250, 256>>>();
    k_degloop<<<200000, 256>>>(ei, ea);
    k_scan<<<1, 1024>>>();
    k_loopdiv<<<6250, 256>>>();
    k_self<<<(N_NODES + 255) / 256, 256>>>();
    k_scatter<<<(N_EDGESC + 255) / 256, 256>>>(ei);

    for (int l = 0; l < 3; l++) {
        int hin  = l;                 // 0: x, 1: hA, 2: hB
        int hout = (l == 1) ? 1 : 0;  // 0->hA, 1->hB, 2->hA
        k_xlxr<<<(N_NODES + 31) / 32, 128>>>(x, hin,
                                             Wl + (size_t)l * F * F, bl + (size_t)l * F,
                                             Wr + (size_t)l * F * F, br + (size_t)l * F);
        k_ee<<<2048, 256>>>(ea, We + (size_t)l * FE * F);
        k_agg<<<(N_NODES * 32 + 255) / 256, 256>>>(att + (size_t)l * F,
                                                   bias + (size_t)l * F, hout);
    }

    k_pool<<<(N_NODES * F) / 256, 256>>>(batch);
    k_final<<<(NG * NC + 127) / 128, 128>>>(lw, lb, out);
}

// round 5
// speedup vs baseline: 1.4218x; 1.4218x over previous
#include <cuda_runtime.h>
#include <cuda_bf16.h>

#define N_NODES  50000
#define N_EDGESC 1600000
#define ET       1650000            // edges + self loops
#define F        128
#define FE       32
#define NG       512
#define NC       10
#define SLOPE    0.2f

typedef unsigned long long u64;

// ---------------- f32x2 helpers (Blackwell packed fp32) ----------------------
__device__ __forceinline__ u64 pack2(float x, float y) {
    u64 r; asm("mov.b64 %0, {%1, %2};" : "=l"(r) : "f"(x), "f"(y)); return r;
}
__device__ __forceinline__ float2 unpack2(u64 v) {
    float2 f; asm("mov.b64 {%0, %1}, %2;" : "=f"(f.x), "=f"(f.y) : "l"(v)); return f;
}
__device__ __forceinline__ u64 ffma2(u64 a, u64 b, u64 c) {
    u64 d; asm("fma.rn.f32x2 %0, %1, %2, %3;" : "=l"(d) : "l"(a), "l"(b), "l"(c)); return d;
}

// ---------------- scratch (device globals: allocation-free rule) -------------
__device__ float g_score[ET];
__device__ float g_xl[(size_t)N_NODES * F];
__device__ float g_xr[(size_t)N_NODES * F];
__device__ float g_hA[(size_t)N_NODES * F];
__device__ float g_hB[(size_t)N_NODES * F];
__device__ float g_loop[(size_t)N_NODES * FE];   // self-loop attrs (mean of incoming)
__device__ int   g_deg[N_NODES];
__device__ int   g_rowptr[N_NODES + 1];
__device__ int   g_cnt[N_NODES];
__device__ int   g_srcs[ET];
__device__ int   g_eids[ET];
__device__ int   g_dsts[ET];
__device__ int   g_gptr[NG + 1];
__device__ float g_pool[NG * F];
__device__ int   g_is64;                   // 1 if index arrays are int64, 0 if int32

// ---------------- index dtype handling --------------------------------------
__global__ void k_probe(const void* __restrict__ ei) {
    const unsigned* w = (const unsigned*)ei;
    if (threadIdx.x == 0) {
        int all0 = 1;
        #pragma unroll
        for (int i = 0; i < 64; i++) all0 &= (w[2 * i + 1] == 0u);
        g_is64 = all0;
    }
}
__device__ __forceinline__ int getIdx(const void* __restrict__ p, long long i) {
    if (g_is64) return (int)((const long long*)p)[i];
    return ((const int*)p)[i];
}

// ---------------- preprocessing ---------------------------------------------
__global__ void k_zero() {
    int i = blockIdx.x * blockDim.x + threadIdx.x;
    if (i < N_NODES) { g_deg[i] = 0; g_cnt[i] = 0; }
}

__global__ void k_deg(const void* __restrict__ ei) {
    int e = blockIdx.x * blockDim.x + threadIdx.x;
    if (e >= N_EDGESC) return;
    atomicAdd(&g_deg[getIdx(ei, (long long)N_EDGESC + e)], 1);
}

// exclusive scan of (deg+1) -> rowptr; single block, warp-shfl based
__global__ void k_scan() {
    __shared__ int sw[32];
    __shared__ int sc;
    int tid = threadIdx.x, lane = tid & 31, wid = tid >> 5;
    if (tid == 0) sc = 0;
    __syncthreads();
    for (int base = 0; base < N_NODES; base += 1024) {
        int idx = base + tid;
        int orig = (idx < N_NODES) ? (g_deg[idx] + 1) : 0;
        int v = orig;
        #pragma unroll
        for (int off = 1; off < 32; off <<= 1) {
            int t = __shfl_up_sync(0xffffffffu, v, off);
            if (lane >= off) v += t;
        }
        if (lane == 31) sw[wid] = v;
        __syncthreads();
        if (wid == 0) {
            int w = sw[lane];
            #pragma unroll
            for (int off = 1; off < 32; off <<= 1) {
                int t = __shfl_up_sync(0xffffffffu, w, off);
                if (lane >= off) w += t;
            }
            sw[lane] = w;
        }
        __syncthreads();
        int c0 = sc;
        int incl = v + (wid ? sw[wid - 1] : 0);
        if (idx < N_NODES) g_rowptr[idx] = c0 + incl - orig;
        int tot = sw[31];
        __syncthreads();
        if (tid == 0) sc = c0 + tot;
        __syncthreads();
    }
    if (threadIdx.x == 0) g_rowptr[N_NODES] = sc;   // == ET
}

// place self-loops first in each CSR row
__global__ void k_self() {
    int v = blockIdx.x * blockDim.x + threadIdx.x;
    if (v >= N_NODES) return;
    int p = g_rowptr[v];
    g_srcs[p] = v;
    g_eids[p] = N_EDGESC + v;
    g_dsts[p] = v;
}

// counting-sort scatter of real edges by dst
__global__ void k_scatter(const void* __restrict__ ei) {
    int e = blockIdx.x * blockDim.x + threadIdx.x;
    if (e >= N_EDGESC) return;
    int src = getIdx(ei, e);
    int dst = getIdx(ei, (long long)N_EDGESC + e);
    int p = g_rowptr[dst] + 1 + atomicAdd(&g_cnt[dst], 1);
    g_srcs[p] = src;
    g_eids[p] = e;
    g_dsts[p] = dst;
}

// self-loop attr = mean of incoming edge attrs, computed from CSR (no atomics)
__global__ void __launch_bounds__(256) k_loopcsr(const float* __restrict__ ea) {
    int wid = (blockIdx.x * blockDim.x + threadIdx.x) >> 5;
    if (wid >= N_NODES) return;
    int lane = threadIdx.x & 31;
    int beg = g_rowptr[wid] + 1, end = g_rowptr[wid + 1];
    float acc = 0.f;
    for (int i = beg; i < end; i++) {
        int e = g_eids[i];
        acc += ea[(long long)e * FE + lane];
    }
    float d = (float)(end - beg);
    g_loop[wid * FE + lane] = acc / fmaxf(d, 1.f);
}

// ---------------- node GEMMs: xl = h@Wl + bl, xr = h@Wr + br ------------------
// 128 threads (one output column each) x 32 rows per block; f32x2 row-pairs.
__global__ void __launch_bounds__(128) k_xlxr(
    const float* __restrict__ x_ext, int hin_sel,
    const float* __restrict__ Wl, const float* __restrict__ bl,
    const float* __restrict__ Wr, const float* __restrict__ br) {
    const float* h = (hin_sel == 0) ? x_ext : (hin_sel == 1 ? g_hA : g_hB);
    __shared__ float shT[F][34];    // shT[k][r] = h[r0+r][k]; pad keeps 8B align (34*4=136)
    int j = threadIdx.x;
    int r0 = blockIdx.x * 32;
    #pragma unroll
    for (int r = 0; r < 32; r++) {
        int row = r0 + r;
        shT[j][r] = (row < N_NODES) ? h[(long long)row * F + j] : 0.f;
    }
    __syncthreads();
    u64 aL[16], aR[16];
    {
        u64 bl2 = pack2(bl[j], bl[j]);
        u64 br2 = pack2(br[j], br[j]);
        #pragma unroll
        for (int rp = 0; rp < 16; rp++) { aL[rp] = bl2; aR[rp] = br2; }
    }
    #pragma unroll 2
    for (int k = 0; k < F; k++) {
        float wl = Wl[k * F + j];
        float wr = Wr[k * F + j];
        u64 wl2 = pack2(wl, wl);
        u64 wr2 = pack2(wr, wr);
        #pragma unroll
        for (int rp = 0; rp < 16; rp++) {
            u64 hv2 = *(const u64*)&shT[k][2 * rp];
            aL[rp] = ffma2(hv2, wl2, aL[rp]);
            aR[rp] = ffma2(hv2, wr2, aR[rp]);
        }
    }
    #pragma unroll
    for (int rp = 0; rp < 16; rp++) {
        float2 l = unpack2(aL[rp]);
        float2 r = unpack2(aR[rp]);
        int row = r0 + 2 * rp;
        if (row < N_NODES)     { g_xl[(long long)row * F + j] = l.x; g_xr[(long long)row * F + j] = r.x; }
        if (row + 1 < N_NODES) { g_xl[(long long)(row + 1) * F + j] = l.y; g_xr[(long long)(row + 1) * F + j] = r.y; }
    }
}

// ---------------- per-edge attention score (fused edge GEMM) -----------------
// score[i] = att . LeakyReLU(xl[src] + xr[dst] + attr(eid) @ We), warp per edge.
__global__ void __launch_bounds__(128) k_score(
    const float* __restrict__ ea, const float* __restrict__ We,
    const float* __restrict__ att) {
    int lane = threadIdx.x & 31;
    u64 w[FE][2];                       // We[k][4*lane .. 4*lane+3] as 2 packed pairs
    #pragma unroll
    for (int k = 0; k < FE; k++) {
        float4 wv = *(const float4*)(We + k * F + 4 * lane);
        w[k][0] = pack2(wv.x, wv.y);
        w[k][1] = pack2(wv.z, wv.w);
    }
    float4 at = *(const float4*)(att + 4 * lane);
    int wid = (blockIdx.x * blockDim.x + threadIdx.x) >> 5;
    int nw  = (gridDim.x * blockDim.x) >> 5;
    for (int i = wid; i < ET; i += nw) {
        int e   = g_eids[i];
        int src = g_srcs[i];
        int dst = g_dsts[i];
        const float* ap = (e < N_EDGESC) ? (ea + (long long)e * FE)
                                         : (g_loop + (long long)(e - N_EDGESC) * FE);
        float a = ap[lane];
        float4 xl = *(const float4*)(g_xl + (long long)src * F + 4 * lane);
        float4 xr = *(const float4*)(g_xr + (long long)dst * F + 4 * lane);
        u64 acc0 = pack2(xl.x + xr.x, xl.y + xr.y);
        u64 acc1 = pack2(xl.z + xr.z, xl.w + xr.w);
        #pragma unroll
        for (int k = 0; k < FE; k++) {
            float ak = __shfl_sync(0xffffffffu, a, k);
            u64 ak2 = pack2(ak, ak);
            acc0 = ffma2(ak2, w[k][0], acc0);
            acc1 = ffma2(ak2, w[k][1], acc1);
        }
        float2 s01 = unpack2(acc0);
        float2 s23 = unpack2(acc1);
        float t0 = s01.x > 0.f ? s01.x : SLOPE * s01.x;
        float t1 = s01.y > 0.f ? s01.y : SLOPE * s01.y;
        float t2 = s23.x > 0.f ? s23.x : SLOPE * s23.x;
        float t3 = s23.y > 0.f ? s23.y : SLOPE * s23.y;
        float p = t0 * at.x + t1 * at.y + t2 * at.z + t3 * at.w;
        #pragma unroll
        for (int off = 16; off; off >>= 1) p += __shfl_xor_sync(0xffffffffu, p, off);
        if (lane == 0) g_score[i] = p;
    }
}

// ---------------- softmax-weighted aggregation (warp per node) ---------------
__global__ void __launch_bounds__(256) k_agg(
    const float* __restrict__ bias, int hout_sel) {
    int wid = (blockIdx.x * blockDim.x + threadIdx.x) >> 5;
    if (wid >= N_NODES) return;
    float* hout = (hout_sel == 1) ? g_hB : g_hA;
    int lane = threadIdx.x & 31;
    int beg = g_rowptr[wid], end = g_rowptr[wid + 1];
    float m = -3.0e38f, denom = 0.f;
    float4 acc = make_float4(0.f, 0.f, 0.f, 0.f);
    for (int t = beg; t < end; t += 32) {
        int idx = t + lane;
        bool ok = idx < end;
        float s  = ok ? g_score[idx] : -3.0e38f;
        int   sr = ok ? g_srcs[idx]  : 0;
        float tm = s;
        #pragma unroll
        for (int off = 16; off; off >>= 1) tm = fmaxf(tm, __shfl_xor_sync(0xffffffffu, tm, off));
        float mn = fmaxf(m, tm);
        float rs = __expf(m - mn);        // first tile: exp(-huge) -> 0
        denom *= rs;
        acc.x *= rs; acc.y *= rs; acc.z *= rs; acc.w *= rs;
        float pe = ok ? __expf(s - mn) : 0.f;
        float ps = pe;
        #pragma unroll
        for (int off = 16; off; off >>= 1) ps += __shfl_xor_sync(0xffffffffu, ps, off);
        denom += ps;
        int cnt = min(32, end - t);
        for (int j = 0; j < cnt; j++) {
            float pj = __shfl_sync(0xffffffffu, pe, j);
            int   sj = __shfl_sync(0xffffffffu, sr, j);
            float4 xl = *(const float4*)(g_xl + (long long)sj * F + 4 * lane);
            acc.x += pj * xl.x;
            acc.y += pj * xl.y;
            acc.z += pj * xl.z;
            acc.w += pj * xl.w;
        }
        m = mn;
    }
    float4 bi = *(const float4*)(bias + 4 * lane);
    float inv = 1.f / denom;
    float4 o;
    o.x = fmaxf(acc.x * inv + bi.x, 0.f);
    o.y = fmaxf(acc.y * inv + bi.y, 0.f);
    o.z = fmaxf(acc.z * inv + bi.z, 0.f);
    o.w = fmaxf(acc.w * inv + bi.w, 0.f);
    *(float4*)(hout + (long long)wid * F + 4 * lane) = o;
}

// ---------------- pool + classifier ----------------------------------------
__global__ void k_gptr(const void* __restrict__ batch) {
    int g = blockIdx.x * blockDim.x + threadIdx.x;
    if (g > NG) return;
    int lo = 0, hi = N_NODES;
    while (lo < hi) {
        int mid = (lo + hi) >> 1;
        if (getIdx(batch, mid) < g) lo = mid + 1; else hi = mid;
    }
    g_gptr[g] = lo;
}

__global__ void __launch_bounds__(128) k_poolg() {
    int g = blockIdx.x;
    int j = threadIdx.x;
    int b = g_gptr[g], e = g_gptr[g + 1];
    float acc = 0.f;
    for (int v = b; v < e; v++) acc += g_hA[(long long)v * F + j];
    float inv = 1.f / fmaxf((float)(e - b), 1.f);
    g_pool[g * F + j] = acc * inv;
}

__global__ void k_final(const float* __restrict__ lw, const float* __restrict__ lb,
                        float* __restrict__ out) {
    int t = blockIdx.x * blockDim.x + threadIdx.x;
    if (t >= NG * NC) return;
    int g = t / NC, cls = t % NC;
    float acc = lb[cls];
    #pragma unroll 8
    for (int c = 0; c < F; c++)
        acc += g_pool[g * F + c] * lw[c * NC + cls];
    out[t] = acc;
}

// ---------------- host -------------------------------------------------------
extern "C" void kernel_launch(void* const* d_in, const int* in_sizes, int n_in,
                              void* d_out, int out_size) {
    (void)in_sizes; (void)n_in; (void)out_size;
    const float* x     = (const float*)d_in[0];
    const void*  ei    = d_in[1];               // int32 or int64 (probed)
    const void*  batch = d_in[2];               // int32 or int64 (probed)
    // d_in[3] = dropout (identity in eval)
    const float* ea   = (const float*)d_in[4];
    const float* Wl   = (const float*)d_in[5];
    const float* bl   = (const float*)d_in[6];
    const float* Wr   = (const float*)d_in[7];
    const float* br   = (const float*)d_in[8];
    const float* We   = (const float*)d_in[9];
    const float* att  = (const float*)d_in[10];
    const float* bias = (const float*)d_in[11];
    const float* lw   = (const float*)d_in[12];
    const float* lb   = (const float*)d_in[13];
    float* out = (float*)d_out;

    k_probe<<<1, 32>>>(ei);
    k_zero<<<(N_NODES + 255) / 256, 256>>>();
    k_deg<<<(N_EDGESC + 255) / 256, 256>>>(ei);
    k_scan<<<1, 1024>>>();
    k_self<<<(N_NODES + 255) / 256, 256>>>();
    k_scatter<<<(N_EDGESC + 255) / 256, 256>>>(ei);
    k_loopcsr<<<(N_NODES * 32 + 255) / 256, 256>>>(ea);

    for (int l = 0; l < 3; l++) {
        int hin  = l;                 // 0: x, 1: hA, 2: hB
        int hout = (l == 1) ? 1 : 0;  // layer0 -> hA, layer1 -> hB, layer2 -> hA
        k_xlxr<<<(N_NODES + 31) / 32, 128>>>(x, hin,
                                             Wl + (size_t)l * F * F, bl + (size_t)l * F,
                                             Wr + (size_t)l * F * F, br + (size_t)l * F);
        k_score<<<4096, 128>>>(ea, We + (size_t)l * FE * F, att + (size_t)l * F);
        k_agg<<<(N_NODES * 32 + 255) / 256, 256>>>(bias + (size_t)l * F, hout);
    }

    k_gptr<<<3, 256>>>(batch);
    k_poolg<<<NG, 128>>>();
    k_final<<<(NG * NC + 127) / 128, 128>>>(lw, lb, out);
}